// round 8
// baseline (speedup 1.0000x reference)
#include <cuda_runtime.h>
#include <math.h>

// ---------------------------------------------------------------------------
// RecurrentPPOAgent fused pipeline, fp32 baseline.
// Stages: encoder (conv1+pool+conv2+conv3+fc+embed) -> GRU GEMM -> gates -> heads
// ---------------------------------------------------------------------------

#define BMAX 131072

// scratch (static device globals; allocation-free per harness rules)
__device__ float g_inp[BMAX * 80];     // encoder output [obs_enc(64) | act_emb(16)]
__device__ float g_gx[BMAX * 384];     // inp @ wih^T
__device__ float g_gh[BMAX * 384];     // hidden @ whh^T

// ===========================================================================
// Encoder: 256 threads = 16 samples x 16 roles. Dynamic smem layout (floats):
//   0     w1 (192)        [o][c][kh][kw]
//   192   b1 (16)
//   208   w2t (2048)      [c][k][o]  o contiguous -> conflict-free
//   2256  b2 (32)
//   2288  w3t (8192)      [c][k][o]
//   10480 b3 (64)
//   10544 fct (4096)      [k][j]
//   14640 fcb (64)
//   14704 emb (112)
//   14816 obs (16*148)
//   17184 p   (16*144)    pooled conv1
//   19488 y2  (16*128)
//   21536 y3  (16*64)
//   22560 inp (16*80)
// total 23840 floats = 95360 B
// ===========================================================================
#define ENC_SMEM_FLOATS 23840

__global__ __launch_bounds__(256) void enc_kernel(
    const float* __restrict__ obs, const int* __restrict__ pact,
    const float* __restrict__ c1w, const float* __restrict__ c1b,
    const float* __restrict__ c2w, const float* __restrict__ c2b,
    const float* __restrict__ c3w, const float* __restrict__ c3b,
    const float* __restrict__ fcw, const float* __restrict__ fcb,
    const float* __restrict__ emb)
{
    extern __shared__ float sm[];
    float* sw1  = sm;
    float* sb1  = sm + 192;
    float* sw2  = sm + 208;
    float* sb2  = sm + 2256;
    float* sw3  = sm + 2288;
    float* sb3  = sm + 10480;
    float* sfc  = sm + 10544;
    float* sfb  = sm + 14640;
    float* semb = sm + 14704;
    float* sobs = sm + 14816;
    float* sp   = sm + 17184;
    float* sy2  = sm + 19488;
    float* sy3  = sm + 21536;
    float* sinp = sm + 22560;

    const int tid = threadIdx.x;

    // ---- cooperative weight staging (with transposes) ----
    for (int i = tid; i < 192; i += 256) sw1[i] = c1w[i];
    if (tid < 16) sb1[tid] = c1b[tid];
    for (int i = tid; i < 2048; i += 256) {
        int o = i >> 6, c = (i >> 2) & 15, k = i & 3;
        sw2[c * 128 + k * 32 + o] = c2w[i];
    }
    if (tid < 32) sb2[tid] = c2b[tid];
    for (int i = tid; i < 8192; i += 256) {
        int o = i >> 7, c = (i >> 2) & 31, k = i & 3;
        sw3[c * 256 + k * 64 + o] = c3w[i];
    }
    if (tid < 64) sb3[tid] = c3b[tid];
    for (int i = tid; i < 4096; i += 256) {
        int j = i >> 6, k = i & 63;
        sfc[k * 64 + j] = fcw[i];
    }
    if (tid < 64) sfb[tid] = fcb[tid];
    for (int i = tid; i < 112; i += 256) semb[i] = emb[i];
    for (int i = tid; i < 16 * 147; i += 256) {
        int ss = i / 147, idx = i - ss * 147;
        sobs[ss * 148 + idx] = obs[(blockIdx.x * 16 + ss) * 147 + idx];
    }
    __syncthreads();

    const int t  = tid & 15;   // role
    const int sl = tid >> 4;   // local sample
    const float* ob = sobs + sl * 148;

    // ---- stage 1: conv1 (channel t) fused with 2x2 maxpool ----
    {
        float w[12];
#pragma unroll
        for (int i = 0; i < 12; i++) w[i] = sw1[t * 12 + i];
        const float b = sb1[t];
#pragma unroll
        for (int pi = 0; pi < 3; pi++)
#pragma unroll
        for (int pj = 0; pj < 3; pj++) {
            float m = -1e30f;
#pragma unroll
            for (int di = 0; di < 2; di++)
#pragma unroll
            for (int dj = 0; dj < 2; dj++) {
                const int i0 = 2 * pi + di, j0 = 2 * pj + dj;
                float acc = b;
#pragma unroll
                for (int c = 0; c < 3; c++)
#pragma unroll
                for (int kh = 0; kh < 2; kh++)
#pragma unroll
                for (int kw = 0; kw < 2; kw++)
                    acc += ob[(i0 + kh) * 21 + (j0 + kw) * 3 + c] * w[c * 4 + kh * 2 + kw];
                m = fmaxf(m, acc);
            }
            sp[sl * 144 + t * 9 + pi * 3 + pj] = fmaxf(m, 0.f);  // relu(max)==max(relu)
        }
    }
    __syncthreads();

    // ---- stage 2: conv2, outputs o = t and t+16, all 4 positions ----
    {
        float a0[4], a1[4];
        const float b0 = sb2[t], b1v = sb2[t + 16];
#pragma unroll
        for (int p = 0; p < 4; p++) { a0[p] = b0; a1[p] = b1v; }
        const float* pp = sp + sl * 144;
#pragma unroll 4
        for (int c = 0; c < 16; c++) {
            float pv[9];
#pragma unroll
            for (int q = 0; q < 9; q++) pv[q] = pp[c * 9 + q];
#pragma unroll
            for (int kh = 0; kh < 2; kh++)
#pragma unroll
            for (int kw = 0; kw < 2; kw++) {
                const int k = kh * 2 + kw;
                const float wa = sw2[c * 128 + k * 32 + t];
                const float wb = sw2[c * 128 + k * 32 + t + 16];
#pragma unroll
                for (int i0 = 0; i0 < 2; i0++)
#pragma unroll
                for (int j0 = 0; j0 < 2; j0++) {
                    const float av = pv[(i0 + kh) * 3 + (j0 + kw)];
                    a0[i0 * 2 + j0] += wa * av;
                    a1[i0 * 2 + j0] += wb * av;
                }
            }
        }
#pragma unroll
        for (int p = 0; p < 4; p++) {
            sy2[sl * 128 + t * 4 + p]        = fmaxf(a0[p], 0.f);
            sy2[sl * 128 + (t + 16) * 4 + p] = fmaxf(a1[p], 0.f);
        }
    }
    __syncthreads();

    // ---- stage 3: conv3 (1x1 spatially; K = 32ch x 2x2), outputs o = t+16q ----
    {
        float acc[4];
#pragma unroll
        for (int q = 0; q < 4; q++) acc[q] = sb3[t + 16 * q];
        const float* y2 = sy2 + sl * 128;
#pragma unroll 8
        for (int c = 0; c < 32; c++) {
            const float4 yv = *(const float4*)&y2[c * 4];
            const float yw[4] = {yv.x, yv.y, yv.z, yv.w};
#pragma unroll
            for (int k = 0; k < 4; k++)
#pragma unroll
            for (int q = 0; q < 4; q++)
                acc[q] += yw[k] * sw3[c * 256 + k * 64 + t + 16 * q];
        }
#pragma unroll
        for (int q = 0; q < 4; q++) sy3[sl * 64 + t + 16 * q] = fmaxf(acc[q], 0.f);
    }
    __syncthreads();

    // ---- stage 4: fc(64x64) + action embedding ----
    {
        float acc[4];
#pragma unroll
        for (int q = 0; q < 4; q++) acc[q] = sfb[t + 16 * q];
        const float* y3 = sy3 + sl * 64;
#pragma unroll 8
        for (int k = 0; k < 64; k++) {
            const float av = y3[k];
#pragma unroll
            for (int q = 0; q < 4; q++) acc[q] += av * sfc[k * 64 + t + 16 * q];
        }
#pragma unroll
        for (int q = 0; q < 4; q++) sinp[sl * 80 + t + 16 * q] = fmaxf(acc[q], 0.f);
        const int s = blockIdx.x * 16 + sl;
        const int pa = pact[s];
        sinp[sl * 80 + 64 + t] = semb[pa * 16 + t];
    }
    __syncthreads();

    for (int i = tid; i < 16 * 80; i += 256) {
        int ss = i / 80, idx = i - ss * 80;
        g_inp[(blockIdx.x * 16 + ss) * 80 + idx] = sinp[i];
    }
}

// ===========================================================================
// GRU GEMM: C[s][n] = sum_k A[s][k] * W[n][k].
// grid = (B/128, 6): chunks 0-2 -> g_gx = g_inp @ wih^T (K=80),
//                    chunks 3-5 -> g_gh = hidden @ whh^T (K=128).
// 256 threads, Mtile=128, Ntile=128, kc=16, 8x8 micro-tile per thread.
// ===========================================================================
__global__ __launch_bounds__(256) void gru_gemm_kernel(
    const float* __restrict__ hidden,
    const float* __restrict__ wih, const float* __restrict__ whh)
{
    __shared__ __align__(16) float As[16][128];
    __shared__ __align__(16) float Bs[16][128];

    const int tid = threadIdx.x;
    const int chunk = blockIdx.y;
    const float* A; const float* W; float* C; int K; int n0;
    if (chunk < 3) { A = g_inp;  K = 80;  n0 = chunk * 128;       W = wih + n0 * 80;  C = g_gx; }
    else           { A = hidden; K = 128; n0 = (chunk - 3) * 128; W = whh + n0 * 128; C = g_gh; }
    const int m0 = blockIdx.x * 128;

    const int f = tid & 3,  r  = tid >> 2;   // staging coords
    const int tx = tid & 15, ty = tid >> 4;  // compute coords

    float acc[8][8];
#pragma unroll
    for (int i = 0; i < 8; i++)
#pragma unroll
    for (int j = 0; j < 8; j++) acc[i][j] = 0.f;

    for (int k0 = 0; k0 < K; k0 += 16) {
        const float4 va0 = *(const float4*)&A[(m0 + r) * K + k0 + f * 4];
        const float4 va1 = *(const float4*)&A[(m0 + r + 64) * K + k0 + f * 4];
        const float4 vb0 = *(const float4*)&W[r * K + k0 + f * 4];
        const float4 vb1 = *(const float4*)&W[(r + 64) * K + k0 + f * 4];
        __syncthreads();
        As[f * 4 + 0][r] = va0.x; As[f * 4 + 1][r] = va0.y;
        As[f * 4 + 2][r] = va0.z; As[f * 4 + 3][r] = va0.w;
        As[f * 4 + 0][r + 64] = va1.x; As[f * 4 + 1][r + 64] = va1.y;
        As[f * 4 + 2][r + 64] = va1.z; As[f * 4 + 3][r + 64] = va1.w;
        Bs[f * 4 + 0][r] = vb0.x; Bs[f * 4 + 1][r] = vb0.y;
        Bs[f * 4 + 2][r] = vb0.z; Bs[f * 4 + 3][r] = vb0.w;
        Bs[f * 4 + 0][r + 64] = vb1.x; Bs[f * 4 + 1][r + 64] = vb1.y;
        Bs[f * 4 + 2][r + 64] = vb1.z; Bs[f * 4 + 3][r + 64] = vb1.w;
        __syncthreads();
#pragma unroll
        for (int k = 0; k < 16; k++) {
            const float4 a0 = *(const float4*)&As[k][ty * 8];
            const float4 a1 = *(const float4*)&As[k][ty * 8 + 4];
            const float4 b0 = *(const float4*)&Bs[k][tx * 8];
            const float4 b1 = *(const float4*)&Bs[k][tx * 8 + 4];
            const float av[8] = {a0.x, a0.y, a0.z, a0.w, a1.x, a1.y, a1.z, a1.w};
            const float bv[8] = {b0.x, b0.y, b0.z, b0.w, b1.x, b1.y, b1.z, b1.w};
#pragma unroll
            for (int i = 0; i < 8; i++)
#pragma unroll
            for (int j = 0; j < 8; j++) acc[i][j] += av[i] * bv[j];
        }
    }

#pragma unroll
    for (int i = 0; i < 8; i++) {
        const int s = m0 + ty * 8 + i;
        float* cp = &C[s * 384 + n0 + tx * 8];
        *(float4*)cp       = make_float4(acc[i][0], acc[i][1], acc[i][2], acc[i][3]);
        *(float4*)(cp + 4) = make_float4(acc[i][4], acc[i][5], acc[i][6], acc[i][7]);
    }
}

// ===========================================================================
// Gates: elementwise GRU cell. thread = (sample, h-unit). h_new -> d_out[B*8 ...]
// ===========================================================================
__global__ __launch_bounds__(256) void gate_kernel(
    const float* __restrict__ hidden,
    const float* __restrict__ bih, const float* __restrict__ bhh,
    float* __restrict__ out, int B)
{
    const long long idx = (long long)blockIdx.x * 256 + threadIdx.x;
    const int j = (int)(idx & 127);
    const long long s = idx >> 7;
    const float* gx = g_gx + s * 384;
    const float* gh = g_gh + s * 384;
    const float xr = gx[j]       + bih[j];
    const float xz = gx[128 + j] + bih[128 + j];
    const float xn = gx[256 + j] + bih[256 + j];
    const float hr = gh[j]       + bhh[j];
    const float hz = gh[128 + j] + bhh[128 + j];
    const float hn = gh[256 + j] + bhh[256 + j];
    const float rg = 1.f / (1.f + expf(-(xr + hr)));
    const float zg = 1.f / (1.f + expf(-(xz + hz)));
    const float ng = tanhf(xn + rg * hn);
    const float h  = hidden[s * 128 + j];
    out[(long long)B * 8 + s * 128 + j] = (1.f - zg) * ng + zg * h;
}

// ===========================================================================
// Heads: Mtile=64 samples. GEMM (64x128x128, rows 0-63=a1, 64-127=c1) ->
// tanh -> smem -> tiny GEMM (logits 7 + value 1).
// ===========================================================================
__global__ __launch_bounds__(256) void heads_kernel(
    const float* __restrict__ a1w, const float* __restrict__ a1b,
    const float* __restrict__ a2w, const float* __restrict__ a2b,
    const float* __restrict__ c1w, const float* __restrict__ c1b,
    const float* __restrict__ c2w, const float* __restrict__ c2b,
    float* __restrict__ out, int B)
{
    __shared__ __align__(16) float As[16][64];
    __shared__ __align__(16) float Bs[16][128];
    __shared__ float stt[64 * 129];
    __shared__ float sbias[128];
    __shared__ float w2t[512];
    __shared__ float b2s[8];

    const int tid = threadIdx.x;
    const float* hsrc = out + (long long)B * 8;
    const int m0 = blockIdx.x * 64;

    if (tid < 64)       sbias[tid] = a1b[tid];
    else if (tid < 128) sbias[tid] = c1b[tid - 64];
    for (int i = tid; i < 512; i += 256) {
        const int o = i >> 6, k = i & 63;
        w2t[k * 8 + o] = (o < 7) ? a2w[o * 64 + k] : c2w[k];
    }
    if (tid < 8) b2s[tid] = (tid < 7) ? a2b[tid] : c2b[0];

    const int f = tid & 3,  r  = tid >> 2;   // r in 0..63
    const int tx = tid & 15, ty = tid >> 4;

    float acc[4][8];
#pragma unroll
    for (int i = 0; i < 4; i++)
#pragma unroll
    for (int j = 0; j < 8; j++) acc[i][j] = 0.f;

    for (int k0 = 0; k0 < 128; k0 += 16) {
        const float4 va  = *(const float4*)&hsrc[(long long)(m0 + r) * 128 + k0 + f * 4];
        const float4 vb0 = *(const float4*)&a1w[r * 128 + k0 + f * 4];
        const float4 vb1 = *(const float4*)&c1w[r * 128 + k0 + f * 4];
        __syncthreads();
        As[f * 4 + 0][r] = va.x; As[f * 4 + 1][r] = va.y;
        As[f * 4 + 2][r] = va.z; As[f * 4 + 3][r] = va.w;
        Bs[f * 4 + 0][r] = vb0.x; Bs[f * 4 + 1][r] = vb0.y;
        Bs[f * 4 + 2][r] = vb0.z; Bs[f * 4 + 3][r] = vb0.w;
        Bs[f * 4 + 0][r + 64] = vb1.x; Bs[f * 4 + 1][r + 64] = vb1.y;
        Bs[f * 4 + 2][r + 64] = vb1.z; Bs[f * 4 + 3][r + 64] = vb1.w;
        __syncthreads();
#pragma unroll
        for (int k = 0; k < 16; k++) {
            const float4 a  = *(const float4*)&As[k][ty * 4];
            const float4 b0 = *(const float4*)&Bs[k][tx * 8];
            const float4 b1 = *(const float4*)&Bs[k][tx * 8 + 4];
            const float av[4] = {a.x, a.y, a.z, a.w};
            const float bv[8] = {b0.x, b0.y, b0.z, b0.w, b1.x, b1.y, b1.z, b1.w};
#pragma unroll
            for (int i = 0; i < 4; i++)
#pragma unroll
            for (int j = 0; j < 8; j++) acc[i][j] += av[i] * bv[j];
        }
    }

    // tanh epilogue -> stt
#pragma unroll
    for (int i = 0; i < 4; i++) {
        const int m = ty * 4 + i;
#pragma unroll
        for (int j = 0; j < 8; j++) {
            const int n = tx * 8 + j;
            stt[m * 129 + n] = tanhf(acc[i][j] + sbias[n]);
        }
    }
    __syncthreads();

    // phase 2: 8 outputs per sample (7 logits + value), K=64
    const int o  = tid & 7;
    const int slh = tid >> 3;  // 0..31
#pragma unroll
    for (int rep = 0; rep < 2; rep++) {
        const int ss = slh + rep * 32;
        const float* tp = &stt[ss * 129 + ((o < 7) ? 0 : 64)];
        float a = b2s[o];
#pragma unroll 16
        for (int k = 0; k < 64; k++) a += tp[k] * w2t[k * 8 + o];
        const long long sg = m0 + ss;
        if (o < 7) out[sg * 7 + o] = a;
        else       out[(long long)B * 7 + sg] = a;
    }
}

// ===========================================================================
extern "C" void kernel_launch(void* const* d_in, const int* in_sizes, int n_in,
                              void* d_out, int out_size)
{
    const float* obs     = (const float*)d_in[0];
    const int*   pact    = (const int*)  d_in[1];
    const float* hidden  = (const float*)d_in[2];
    const float* c1w     = (const float*)d_in[3];
    const float* c1b     = (const float*)d_in[4];
    const float* c2w     = (const float*)d_in[5];
    const float* c2b     = (const float*)d_in[6];
    const float* c3w     = (const float*)d_in[7];
    const float* c3b     = (const float*)d_in[8];
    const float* fcw     = (const float*)d_in[9];
    const float* fcb     = (const float*)d_in[10];
    const float* emb     = (const float*)d_in[11];
    const float* gru_wih = (const float*)d_in[12];
    const float* gru_whh = (const float*)d_in[13];
    const float* gru_bih = (const float*)d_in[14];
    const float* gru_bhh = (const float*)d_in[15];
    const float* a1w     = (const float*)d_in[16];
    const float* a1b     = (const float*)d_in[17];
    const float* a2w     = (const float*)d_in[18];
    const float* a2b     = (const float*)d_in[19];
    const float* c1wh    = (const float*)d_in[20];
    const float* c1bh    = (const float*)d_in[21];
    const float* c2wh    = (const float*)d_in[22];
    const float* c2bh    = (const float*)d_in[23];
    float* out = (float*)d_out;

    const int B = in_sizes[0] / 147;

    cudaFuncSetAttribute(enc_kernel, cudaFuncAttributeMaxDynamicSharedMemorySize,
                         ENC_SMEM_FLOATS * (int)sizeof(float));

    enc_kernel<<<B / 16, 256, ENC_SMEM_FLOATS * sizeof(float)>>>(
        obs, pact, c1w, c1b, c2w, c2b, c3w, c3b, fcw, fcb, emb);

    dim3 g2(B / 128, 6);
    gru_gemm_kernel<<<g2, 256>>>(hidden, gru_wih, gru_whh);

    gate_kernel<<<(B * 128) / 256, 256>>>(hidden, gru_bih, gru_bhh, out, B);

    heads_kernel<<<B / 64, 256>>>(a1w, a1b, a2w, a2b, c1wh, c1bh, c2wh, c2bh, out, B);
}